// round 13
// baseline (speedup 1.0000x reference)
#include <cuda_runtime.h>
#include <cuda_bf16.h>
#include <stdint.h>

#define E_EXP 8
#define D_DIM 1024
#define F_DIM 4096
#define T_TOK 4096
#define NSLOT (T_TOK * 2)

// ---------------- scratch (static __device__ arrays; no allocation) ----------------
__device__ __nv_bfloat16 g_xa[(size_t)NSLOT * D_DIM];   // per-slot normalized x * ln_w[e], bf16
__device__ __nv_bfloat16 g_h[(size_t)NSLOT * F_DIM];    // gated activations
__device__ float         g_ys[(size_t)NSLOT * D_DIM];   // per-slot FFN output
__device__ float g_inv[T_TOK];
__device__ int   g_cnt[E_EXP];     // zero at load; re-zeroed by combine each call
__device__ int   g_off[E_EXP];
__device__ int   g_perm[NSLOT];
__device__ int   g_slotE[NSLOT];
__device__ int   g_tokE[NSLOT];
__device__ int   g_slot[NSLOT];
__device__ float g_gw[NSLOT];

// ---------------- small helpers ----------------
__device__ __forceinline__ void cp16s(uint32_t dst, const void* src) {
    asm volatile("cp.async.cg.shared.global [%0], [%1], 16;\n" :: "r"(dst), "l"(src));
}
__device__ __forceinline__ void cp_commit() { asm volatile("cp.async.commit_group;\n" ::: "memory"); }
template <int N>
__device__ __forceinline__ void cp_wait() { asm volatile("cp.async.wait_group %0;\n" :: "n"(N) : "memory"); }

__device__ __forceinline__ void ldsm4(uint32_t* r, uint32_t a) {
    asm volatile("ldmatrix.sync.aligned.m8n8.x4.shared.b16 {%0,%1,%2,%3}, [%4];\n"
                 : "=r"(r[0]), "=r"(r[1]), "=r"(r[2]), "=r"(r[3]) : "r"(a));
}
__device__ __forceinline__ void mma16816(float* c, const uint32_t* a, uint32_t b0, uint32_t b1) {
    asm volatile(
        "mma.sync.aligned.m16n8k16.row.col.f32.bf16.bf16.f32 "
        "{%0,%1,%2,%3}, {%4,%5,%6,%7}, {%8,%9}, {%0,%1,%2,%3};\n"
        : "+f"(c[0]), "+f"(c[1]), "+f"(c[2]), "+f"(c[3])
        : "r"(a[0]), "r"(a[1]), "r"(a[2]), "r"(a[3]), "r"(b0), "r"(b1));
}
__device__ __forceinline__ float siluf(float v) { return v / (1.f + __expf(-v)); }
__device__ __forceinline__ void sts8(uint32_t addr, uint32_t u0, uint32_t u1) {
    asm volatile("st.shared.v2.u32 [%0], {%1, %2};" :: "r"(addr), "r"(u0), "r"(u1) : "memory");
}

// ---------------- gating + rmsnorm stats (one warp per token) ----------------
__global__ void __launch_bounds__(256) gate_kernel(const float* __restrict__ x,
                                                   const float* __restrict__ gw) {
    const int wid = threadIdx.x >> 5, lane = threadIdx.x & 31;
    const int t = blockIdx.x * 8 + wid;
    float xr[32];
    float ss = 0.f;
    const float* xp = x + (size_t)t * D_DIM + lane;
#pragma unroll
    for (int i = 0; i < 32; ++i) { xr[i] = xp[i * 32]; ss += xr[i] * xr[i]; }
    float sc[8];
#pragma unroll
    for (int e = 0; e < 8; ++e) {
        const float* gp = gw + e * D_DIM + lane;
        float s = 0.f;
#pragma unroll
        for (int i = 0; i < 32; ++i) s += xr[i] * gp[i * 32];
        sc[e] = s;
    }
#pragma unroll
    for (int o = 16; o > 0; o >>= 1) {
        ss += __shfl_xor_sync(0xffffffffu, ss, o);
#pragma unroll
        for (int e = 0; e < 8; ++e) sc[e] += __shfl_xor_sync(0xffffffffu, sc[e], o);
    }
    if (lane == 0) {
        g_inv[t] = rsqrtf(ss * (1.f / D_DIM) + 1e-6f);
        int i0 = 0; float v0 = sc[0];
#pragma unroll
        for (int e = 1; e < 8; ++e) if (sc[e] > v0) { v0 = sc[e]; i0 = e; }
        int i1 = (i0 == 0) ? 1 : 0; float v1 = sc[i1];
#pragma unroll
        for (int e = 0; e < 8; ++e)
            if (e != i0 && sc[e] > v1) { v1 = sc[e]; i1 = e; }
        const float e1 = __expf(v1 - v0);
        const float z  = 1.f + e1;
        g_tokE[2 * t] = i0; g_tokE[2 * t + 1] = i1;
        g_gw[2 * t] = 1.f / z; g_gw[2 * t + 1] = e1 / z;
        atomicAdd(&g_cnt[i0], 1);
        atomicAdd(&g_cnt[i1], 1);
    }
}

// ---------------- scan + scatter (single block) ----------------
__global__ void __launch_bounds__(1024) scan_scatter_kernel() {
    __shared__ int s_cur[E_EXP];
    const int tid = threadIdx.x;
    if (tid == 0) {
        int s = 0;
        for (int e = 0; e < E_EXP; ++e) { g_off[e] = s; s_cur[e] = s; s += g_cnt[e]; }
    }
    __syncthreads();
    for (int t = tid; t < T_TOK; t += 1024) {
#pragma unroll
        for (int k = 0; k < 2; ++k) {
            int e = g_tokE[2 * t + k];
            int s = atomicAdd(&s_cur[e], 1);
            g_perm[s] = t;
            g_slotE[s] = e;
            g_slot[2 * t + k] = s;
        }
    }
}

// ---------------- per-slot A prep: xa = bf16(x * inv_rms * ln_w[e]) ----------------
__global__ void __launch_bounds__(256) prep_a_kernel(const float* __restrict__ x,
                                                     const float* __restrict__ ln) {
    const int s = blockIdx.x;
    const int t = g_perm[s];
    const int e = g_slotE[s];
    const float inv = g_inv[t];
    const int d = threadIdx.x * 4;
    float4 xv = *reinterpret_cast<const float4*>(x + (size_t)t * D_DIM + d);
    float4 lv = *reinterpret_cast<const float4*>(ln + (size_t)e * D_DIM + d);
    __nv_bfloat162 lo = __floats2bfloat162_rn(xv.x * inv * lv.x, xv.y * inv * lv.y);
    __nv_bfloat162 hi = __floats2bfloat162_rn(xv.z * inv * lv.z, xv.w * inv * lv.w);
    uint2 u;
    u.x = *reinterpret_cast<uint32_t*>(&lo);
    u.y = *reinterpret_cast<uint32_t*>(&hi);
    *reinterpret_cast<uint2*>(g_xa + (size_t)s * D_DIM + d) = u;
}

// ================= GEMM settings =================
// R7-proven core: CTA M=128, warp 32x64-ish, KSTAGE=64, A cp.async NBUF=3 (48KB),
// B converted in-kernel fp32->bf16, smem double-buffered (2 x 16KB). 2 CTAs/SM.
#define KSTAGE 64
#define G_SMEM (49152 + 32768)

// ---------------- GEMM1 (xa @ w1^T, xa @ w3^T fused silu-gate; fp32 weights in) ----------------
__global__ void __launch_bounds__(256, 2) gemm1_kernel(const float* __restrict__ w1,
                                                       const float* __restrict__ w3) {
    extern __shared__ __align__(128) char smem[];
    const int e = blockIdx.z;
    const int cnt = g_cnt[e];
    const int mtile = blockIdx.y;
    if (mtile * 128 >= cnt) return;
    const int ntile = blockIdx.x;
    const int off = g_off[e];
    const int tid = threadIdx.x;
    const int lane = tid & 31;
    const int w = tid >> 5;
    const int wm = w & 3, wn = w >> 2;

    const uint32_t sb = (uint32_t)__cvta_generic_to_shared(smem);
    const uint32_t Abase = sb;                 // 3 x 16KB
    const uint32_t Bbase = sb + 49152;         // 2 x (w1 8KB + w3 8KB)

    const int mrow0 = off + mtile * 128;
    const int mlast = off + cnt - 1;

    const int rr = tid >> 3;
    const int cc = tid & 7;
    const uint32_t swoff = (uint32_t)cc << 4;

    auto load_A = [&](int buf, int kt) {
        const uint32_t base = Abase + (uint32_t)buf * 16384;
        const int k0 = kt * KSTAGE;
#pragma unroll
        for (int p = 0; p < 4; ++p) {
            int r = p * 32 + rr;
            int row = mrow0 + r; if (row > mlast) row = mlast;
            uint32_t so = (uint32_t)(r << 7) + (swoff ^ ((uint32_t)(r & 7) << 4));
            cp16s(base + so, g_xa + (size_t)row * D_DIM + k0 + cc * 8);
        }
        cp_commit();
    };

    const float* w1p = w1 + ((size_t)e * F_DIM + (size_t)ntile * 64) * D_DIM;
    const float* w3p = w3 + ((size_t)e * F_DIM + (size_t)ntile * 64) * D_DIM;

    // B staging regs: 4 x float4 (one 64x64-float half-stage = one matrix)
    float4 R[4];
    const int bq_r  = tid >> 4;           // row 0..15 stride 16? no: q=tid+p*256 below
    (void)bq_r;
    auto ldg_half = [&](const float* src, int kt) {
        const int k0 = kt * KSTAGE;
#pragma unroll
        for (int p = 0; p < 4; ++p) {
            int q = tid + p * 256;
            int r = q >> 4, c4 = q & 15;
            R[p] = __ldg(reinterpret_cast<const float4*>(src + (size_t)r * D_DIM + k0 + c4 * 4));
        }
    };
    auto sts_half = [&](uint32_t dstbase) {
#pragma unroll
        for (int p = 0; p < 4; ++p) {
            int q = tid + p * 256;
            int r = q >> 4, c4 = q & 15;
            uint32_t addr = dstbase + (uint32_t)(r << 7)
                          + ((((uint32_t)(c4 >> 1)) ^ (uint32_t)(r & 7)) << 4)
                          + ((uint32_t)(c4 & 1) << 3);
            __nv_bfloat162 lo = __floats2bfloat162_rn(R[p].x, R[p].y);
            __nv_bfloat162 hi = __floats2bfloat162_rn(R[p].z, R[p].w);
            sts8(addr, *reinterpret_cast<uint32_t*>(&lo), *reinterpret_cast<uint32_t*>(&hi));
        }
    };

    float acc1[2][4][4], acc3[2][4][4];
#pragma unroll
    for (int a = 0; a < 2; ++a)
#pragma unroll
        for (int b = 0; b < 4; ++b)
#pragma unroll
            for (int c = 0; c < 4; ++c) { acc1[a][b][c] = 0.f; acc3[a][b][c] = 0.f; }

    const int sx  = lane & 7;
    const int hiA = lane >> 4;
    const int rA  = wm * 32 + (lane & 15);
    const int hiB = (lane >> 3) & 1;
    const int rB  = wn * 32 + ((lane >> 4) & 1) * 8 + (lane & 7);
    const uint32_t aRow0 = (uint32_t)(rA << 7), aRow1 = (uint32_t)((rA + 16) << 7);
    const uint32_t bRow0 = (uint32_t)(rB << 7), bRow1 = (uint32_t)((rB + 16) << 7);

    auto compute_half = [&](uint32_t Ab, uint32_t Bc, int kklo) {
#pragma unroll
        for (int kk = kklo; kk < kklo + 2; ++kk) {
            const uint32_t ao = (uint32_t)(((2 * kk + hiA) ^ sx) << 4);
            const uint32_t bo = (uint32_t)(((2 * kk + hiB) ^ sx) << 4);
            uint32_t a[2][4];
            ldsm4(a[0], Ab + aRow0 + ao);
            ldsm4(a[1], Ab + aRow1 + ao);
            uint32_t b1f[2][4], b3f[2][4];
            ldsm4(b1f[0], Bc + bRow0 + bo);
            ldsm4(b1f[1], Bc + bRow1 + bo);
            ldsm4(b3f[0], Bc + 8192 + bRow0 + bo);
            ldsm4(b3f[1], Bc + 8192 + bRow1 + bo);
#pragma unroll
            for (int im = 0; im < 2; ++im)
#pragma unroll
                for (int j = 0; j < 4; ++j) {
                    mma16816(acc1[im][j], a[im],
                             b1f[j >> 1][(j & 1) * 2], b1f[j >> 1][(j & 1) * 2 + 1]);
                    mma16816(acc3[im][j], a[im],
                             b3f[j >> 1][(j & 1) * 2], b3f[j >> 1][(j & 1) * 2 + 1]);
                }
        }
    };

    // prologue: A(0),A(1) async; B(0) via LDG+cvt+STS
    load_A(0, 0);
    load_A(1, 1);
    ldg_half(w1p, 0); sts_half(Bbase);
    ldg_half(w3p, 0); sts_half(Bbase + 8192);

    const int NK = D_DIM / KSTAGE;   // 16
#pragma unroll 1
    for (int kt = 0; kt < NK; ++kt) {
        if (kt < NK - 1) cp_wait<1>(); else cp_wait<0>();
        __syncthreads();
        if (kt + 2 < NK) load_A((kt + 2) % 3, kt + 2);
        const uint32_t Ab   = Abase + (uint32_t)(kt % 3) * 16384;
        const uint32_t Bcur = Bbase + (uint32_t)(kt & 1) * 16384;
        const uint32_t Bnxt = Bbase + (uint32_t)((kt + 1) & 1) * 16384;
        const bool more = (kt + 1 < NK);
        if (more) ldg_half(w1p, kt + 1);
        compute_half(Ab, Bcur, 0);
        if (more) { sts_half(Bnxt); ldg_half(w3p, kt + 1); }
        compute_half(Ab, Bcur, 2);
        if (more) sts_half(Bnxt + 8192);
    }

    const int mbase = mtile * 128 + wm * 32 + (lane >> 2);
    const int fbase = ntile * 64 + wn * 32 + (lane & 3) * 2;
#pragma unroll
    for (int im = 0; im < 2; ++im)
#pragma unroll
        for (int j = 0; j < 4; ++j)
#pragma unroll
            for (int hh = 0; hh < 2; ++hh) {
                int m = mbase + im * 16 + hh * 8;
                if (m < cnt) {
                    float v0 = siluf(acc1[im][j][hh * 2])     * acc3[im][j][hh * 2];
                    float v1 = siluf(acc1[im][j][hh * 2 + 1]) * acc3[im][j][hh * 2 + 1];
                    *reinterpret_cast<__nv_bfloat162*>(
                        &g_h[(size_t)(off + m) * F_DIM + fbase + j * 8]) =
                        __floats2bfloat162_rn(v0, v1);
                }
            }
}

// ---------------- GEMM2 (h @ w2^T -> ys; fp32 w2 in) ----------------
// CTA M=128, N=128 (warp 32x64, 4m x 2n). Experts reversed (g_h L2-hot).
__global__ void __launch_bounds__(256, 2) gemm2_kernel(const float* __restrict__ w2) {
    extern __shared__ __align__(128) char smem[];
    const int e = E_EXP - 1 - blockIdx.z;
    const int cnt = g_cnt[e];
    const int mtile = blockIdx.y;
    if (mtile * 128 >= cnt) return;
    const int ntile = blockIdx.x;     // 0..7
    const int off = g_off[e];
    const int tid = threadIdx.x;
    const int lane = tid & 31;
    const int w = tid >> 5;
    const int wm = w & 3, wn = w >> 2;

    const uint32_t sb = (uint32_t)__cvta_generic_to_shared(smem);
    const uint32_t Abase = sb;                 // 3 x 16KB
    const uint32_t Bbase = sb + 49152;         // 2 x 16KB (128 rows)

    const int mrow0 = off + mtile * 128;
    const int mlast = off + cnt - 1;

    const int rr = tid >> 3;
    const int cc = tid & 7;
    const uint32_t swoff = (uint32_t)cc << 4;

    auto load_A = [&](int buf, int kt) {
        const uint32_t base = Abase + (uint32_t)buf * 16384;
        const int k0 = kt * KSTAGE;
#pragma unroll
        for (int p = 0; p < 4; ++p) {
            int r = p * 32 + rr;
            int row = mrow0 + r; if (row > mlast) row = mlast;
            uint32_t so = (uint32_t)(r << 7) + (swoff ^ ((uint32_t)(r & 7) << 4));
            cp16s(base + so, g_h + (size_t)row * F_DIM + k0 + cc * 8);
        }
        cp_commit();
    };

    const float* w2p = w2 + ((size_t)e * D_DIM + (size_t)ntile * 128) * F_DIM;

    float4 R[4];
    auto ldg_half = [&](int h, int kt) {      // h = row-half (0: rows 0..63, 1: 64..127)
        const int k0 = kt * KSTAGE;
        const float* src = w2p + (size_t)(h * 64) * F_DIM;
#pragma unroll
        for (int p = 0; p < 4; ++p) {
            int q = tid + p * 256;
            int r = q >> 4, c4 = q & 15;
            R[p] = __ldg(reinterpret_cast<const float4*>(src + (size_t)r * F_DIM + k0 + c4 * 4));
        }
    };
    auto sts_half = [&](uint32_t dstbase) {
#pragma unroll
        for (int p = 0; p < 4; ++p) {
            int q = tid + p * 256;
            int r = q >> 4, c4 = q & 15;
            uint32_t addr = dstbase + (uint32_t)(r << 7)
                          + ((((uint32_t)(c4 >> 1)) ^ (uint32_t)(r & 7)) << 4)
                          + ((uint32_t)(c4 & 1) << 3);
            __nv_bfloat162 lo = __floats2bfloat162_rn(R[p].x, R[p].y);
            __nv_bfloat162 hi = __floats2bfloat162_rn(R[p].z, R[p].w);
            sts8(addr, *reinterpret_cast<uint32_t*>(&lo), *reinterpret_cast<uint32_t*>(&hi));
        }
    };

    float acc[2][8][4];
#pragma unroll
    for (int a = 0; a < 2; ++a)
#pragma unroll
        for (int b = 0; b < 8; ++b)
#pragma unroll
            for (int c = 0; c < 4; ++c) acc[a][b][c] = 0.f;

    const int sx  = lane & 7;
    const int hiA = lane >> 4;
    const int rA  = wm * 32 + (lane & 15);
    const int hiB = (lane >> 3) & 1;
    const int rB  = wn * 64 + ((lane >> 4) & 1) * 8 + (lane & 7);
    const uint32_t aRow0 = (uint32_t)(rA << 7), aRow1 = (uint32_t)((rA + 16) << 7);
    uint32_t bRow[4];
#pragma unroll
    for (int i = 0; i < 4; ++i) bRow[i] = (uint32_t)((rB + i * 16) << 7);

    auto compute_half = [&](uint32_t Ab, uint32_t Bc, int kklo) {
#pragma unroll
        for (int kk = kklo; kk < kklo + 2; ++kk) {
            const uint32_t ao = (uint32_t)(((2 * kk + hiA) ^ sx) << 4);
            const uint32_t bo = (uint32_t)(((2 * kk + hiB) ^ sx) << 4);
            uint32_t a[2][4];
            ldsm4(a[0], Ab + aRow0 + ao);
            ldsm4(a[1], Ab + aRow1 + ao);
            uint32_t bf[4][4];
#pragma unroll
            for (int i16 = 0; i16 < 4; ++i16)
                ldsm4(bf[i16], Bc + bRow[i16] + bo);
#pragma unroll
            for (int im = 0; im < 2; ++im)
#pragma unroll
                for (int j = 0; j < 8; ++j)
                    mma16816(acc[im][j], a[im],
                             bf[j >> 1][(j & 1) * 2], bf[j >> 1][(j & 1) * 2 + 1]);
        }
    };

    load_A(0, 0);
    load_A(1, 1);
    ldg_half(0, 0); sts_half(Bbase);
    ldg_half(1, 0); sts_half(Bbase + 8192);

    const int NK = F_DIM / KSTAGE;   // 64
#pragma unroll 1
    for (int kt = 0; kt < NK; ++kt) {
        if (kt < NK - 1) cp_wait<1>(); else cp_wait<0>();
        __syncthreads();
        if (kt + 2 < NK) load_A((kt + 2) % 3, kt + 2);
        const uint32_t Ab   = Abase + (uint32_t)(kt % 3) * 16384;
        const uint32_t Bcur = Bbase + (uint32_t)(kt & 1) * 16384;
        const uint32_t Bnxt = Bbase + (uint32_t)((kt + 1) & 1) * 16384;
        const bool more = (kt + 1 < NK);
        if (more) ldg_half(0, kt + 1);
        compute_half(Ab, Bcur, 0);
        if (more) { sts_half(Bnxt); ldg_half(1, kt + 1); }
        compute_half(Ab, Bcur, 2);
        if (more) sts_half(Bnxt + 8192);
    }

    const int mbase = mtile * 128 + wm * 32 + (lane >> 2);
    const int dbase = ntile * 128 + wn * 64 + (lane & 3) * 2;
#pragma unroll
    for (int im = 0; im < 2; ++im)
#pragma unroll
        for (int j = 0; j < 8; ++j)
#pragma unroll
            for (int hh = 0; hh < 2; ++hh) {
                int m = mbase + im * 16 + hh * 8;
                if (m < cnt) {
                    float2 v;
                    v.x = acc[im][j][hh * 2];
                    v.y = acc[im][j][hh * 2 + 1];
                    *reinterpret_cast<float2*>(
                        &g_ys[(size_t)(off + m) * D_DIM + dbase + j * 8]) = v;
                }
            }
}

// ---------------- combine (residual + weighted expert outputs) + counter reset ----
__global__ void __launch_bounds__(256) combine_kernel(const float* __restrict__ x,
                                                      float* __restrict__ out) {
    const int t = blockIdx.x;
    if (blockIdx.x == 0 && threadIdx.x < E_EXP) g_cnt[threadIdx.x] = 0;
    const int s0 = g_slot[2 * t], s1 = g_slot[2 * t + 1];
    const float g0 = g_gw[2 * t], g1 = g_gw[2 * t + 1];
    const int d = threadIdx.x * 4;
    float4 xv = *reinterpret_cast<const float4*>(x + (size_t)t * D_DIM + d);
    float4 y0 = *reinterpret_cast<const float4*>(g_ys + (size_t)s0 * D_DIM + d);
    float4 y1 = *reinterpret_cast<const float4*>(g_ys + (size_t)s1 * D_DIM + d);
    float4 o;
    o.x = xv.x + g0 * y0.x + g1 * y1.x;
    o.y = xv.y + g0 * y0.y + g1 * y1.y;
    o.z = xv.z + g0 * y0.z + g1 * y1.z;
    o.w = xv.w + g0 * y0.w + g1 * y1.w;
    *reinterpret_cast<float4*>(out + (size_t)t * D_DIM + d) = o;
}

// ---------------- launch (linear, single stream) ----------------
extern "C" void kernel_launch(void* const* d_in, const int* in_sizes, int n_in,
                              void* d_out, int out_size) {
    (void)in_sizes; (void)n_in; (void)out_size;
    const float* x      = (const float*)d_in[0];
    const float* gate_w = (const float*)d_in[1];
    const float* ln_w   = (const float*)d_in[2];
    const float* w1     = (const float*)d_in[3];
    const float* w3     = (const float*)d_in[4];
    const float* w2     = (const float*)d_in[5];
    float* out = (float*)d_out;

    cudaFuncSetAttribute(gemm1_kernel, cudaFuncAttributeMaxDynamicSharedMemorySize, G_SMEM);
    cudaFuncSetAttribute(gemm2_kernel, cudaFuncAttributeMaxDynamicSharedMemorySize, G_SMEM);

    gate_kernel<<<T_TOK / 8, 256>>>(x, gate_w);                                   // 0
    scan_scatter_kernel<<<1, 1024>>>();                                           // 1
    prep_a_kernel<<<NSLOT, 256>>>(x, ln_w);                                       // 2
    gemm1_kernel<<<dim3(F_DIM / 64, T_TOK / 128, E_EXP), 256, G_SMEM>>>(w1, w3);  // 3
    gemm2_kernel<<<dim3(D_DIM / 128, T_TOK / 128, E_EXP), 256, G_SMEM>>>(w2);     // 4
    combine_kernel<<<T_TOK, 256>>>(x, out);                                       // 5
}